// round 15
// baseline (speedup 1.0000x reference)
#include <cuda_runtime.h>
#include <cuda_fp16.h>
#include <cstdint>

// ---------------------------------------------------------------------------
// Quantized LeNet, B=1024. conv1 dp4a -> fp16 codes; conv2 fp16 implicit-GEMM
// mma m16n8k16, 2 images/CTA with B-fragment register reuse (halves B-side
// LDS); FC1 fp16 mma m16n8k16. All exact: small-int operands (fp16-exact),
// f32 acc < 2^24. Pool-max commutes with monotone quant; LUT epilogues.
// ---------------------------------------------------------------------------

#define DEVBUF __device__ __align__(16)

__device__ unsigned g_absmax[4];                 // zero-init; atomicMax idempotent
DEVBUF int8_t   g_w1q [32 * 9];                  // [oc][tap]
DEVBUF int8_t   g_w2h [64 * 640];                // conv2 B fp16, 640B rows, swizzled
DEVBUF uint16_t g_wl1h[4096 * 1600];             // wl1 codes as fp16 [n][k]
DEVBUF int8_t   g_wl2q[10 * 4096];               // row-major [n][k]
DEVBUF uint16_t g_a1h [1024 * 169 * 32];         // conv1 out NHWC fp16 codes
DEVBUF uint16_t g_a2h [1024 * 1600];             // conv2 out codes as fp16
DEVBUF int8_t   g_a3  [1024 * 4096];             // fc1 out codes [0,15]
DEVBUF uint16_t g_lut1h[1009];                   // conv1 acc -> fp16 code (+504)
DEVBUF uint16_t g_lut2h[32257];                  // conv2 acc -> fp16 code (+16128)
DEVBUF int8_t   g_lut3[179201];                  // fc1  acc -> code (+89600)

// ---------------------------------------------------------------------------
// abs-max with block reduction: ONE atomic per block.
__global__ void __launch_bounds__(256) k_absmax_all(
        const float* __restrict__ w1, const float* __restrict__ w2,
        const float* __restrict__ wl1, const float* __restrict__ wl2) {
    __shared__ float sred[8];
    int b = blockIdx.x, tid = threadIdx.x;
    float m = 0.f;
    int slot;
    if (b < 1024) {                               // wl1: 1638400 float4
        slot = 2;
        const float4* p = (const float4*)wl1;
        for (int i = b * 256 + tid; i < 1638400; i += 1024 * 256) {
            float4 v = p[i];
            m = fmaxf(m, fmaxf(fmaxf(fabsf(v.x), fabsf(v.y)),
                               fmaxf(fabsf(v.z), fabsf(v.w))));
        }
    } else if (b < 1064) {                        // wl2
        slot = 3;
        float4 v = ((const float4*)wl2)[(b - 1024) * 256 + tid];
        m = fmaxf(fmaxf(fabsf(v.x), fabsf(v.y)), fmaxf(fabsf(v.z), fabsf(v.w)));
    } else if (b < 1082) {                        // w2
        slot = 1;
        float4 v = ((const float4*)w2)[(b - 1064) * 256 + tid];
        m = fmaxf(fmaxf(fabsf(v.x), fabsf(v.y)), fmaxf(fabsf(v.z), fabsf(v.w)));
    } else {                                      // w1
        slot = 0;
        if (tid < 72) {
            float4 v = ((const float4*)w1)[tid];
            m = fmaxf(fmaxf(fabsf(v.x), fabsf(v.y)),
                      fmaxf(fabsf(v.z), fabsf(v.w)));
        }
    }
#pragma unroll
    for (int o = 16; o > 0; o >>= 1)
        m = fmaxf(m, __shfl_xor_sync(0xffffffffu, m, o));
    if ((tid & 31) == 0) sred[tid >> 5] = m;
    __syncthreads();
    if (tid == 0) {
        float r = sred[0];
#pragma unroll
        for (int w = 1; w < 8; w++) r = fmaxf(r, sred[w]);
        atomicMax(&g_absmax[slot], __float_as_uint(r));
    }
}

__device__ __forceinline__ float qw7f(float x, float s) {
    float t = rintf(__fdiv_rn(x, s));
    return fminf(fmaxf(t, -7.f), 7.f);
}
__device__ __forceinline__ uint16_t f2h(float f) {
    return __half_as_ushort(__float2half_rn(f));  // exact for small ints
}

// Weight quant + w2 fp16 relayout + LUT build, one kernel.
__global__ void __launch_bounds__(256) k_quant_all(
        const float* __restrict__ w1, const float* __restrict__ w2,
        const float* __restrict__ wl1, const float* __restrict__ wl2,
        const float* __restrict__ ps_in, const float* __restrict__ ps_a1,
        const float* __restrict__ ps_a2, const float* __restrict__ ps_a3) {
    int b = blockIdx.x, tid = threadIdx.x;
    if (b < 6400) {                               // wl1 -> fp16 codes
        float s = __fdiv_rn(__uint_as_float(g_absmax[2]), 7.0f);
        int i = b * 256 + tid;
        float4 v = ((const float4*)wl1)[i];
        ushort4 o;
        o.x = f2h(qw7f(v.x, s)); o.y = f2h(qw7f(v.y, s));
        o.z = f2h(qw7f(v.z, s)); o.w = f2h(qw7f(v.w, s));
        ((ushort4*)g_wl1h)[i] = o;
    } else if (b < 6440) {                        // wl2 int8 char4
        float s = __fdiv_rn(__uint_as_float(g_absmax[3]), 7.0f);
        int i = (b - 6400) * 256 + tid;
        float4 v = ((const float4*)wl2)[i];
        char4 o;
        o.x = (int8_t)qw7f(v.x, s); o.y = (int8_t)qw7f(v.y, s);
        o.z = (int8_t)qw7f(v.z, s); o.w = (int8_t)qw7f(v.w, s);
        ((char4*)g_wl2q)[i] = o;
    } else if (b < 6512) {                        // w2 -> fp16 swizzled layout
        float s = __fdiv_rn(__uint_as_float(g_absmax[1]), 7.0f);
        int i = (b - 6440) * 256 + tid;           // < 18432
        int o = i / 288, rem = i % 288, ci = rem / 9, tap = rem % 9;
        int k = tap * 32 + ci;                    // half index 0..287
        int p = k >> 3;                           // 16B plane (8 halfs)
        *(uint16_t*)(g_w2h + o * 640 + ((p ^ (o & 7)) << 4) + ((k & 7) << 1)) =
            f2h(qw7f(w2[i], s));
    } else if (b == 6512) {                       // w1
        float s = __fdiv_rn(__uint_as_float(g_absmax[0]), 7.0f);
        for (int i = tid; i < 288; i += 256)
            g_w1q[i] = (int8_t)qw7f(w1[i], s);
    } else {                                      // LUT build
        int i = (b - 6513) * 256 + tid;
        float s_in = ps_in[0];
        float sw1 = __fdiv_rn(__uint_as_float(g_absmax[0]), 7.0f);
        float sw2 = __fdiv_rn(__uint_as_float(g_absmax[1]), 7.0f);
        float sw3 = __fdiv_rn(__uint_as_float(g_absmax[2]), 7.0f);
        if (i < 1009) {
            float s_a1 = ps_a1[0];
            float v = (float)(i - 504) * (s_in * sw1);
            float t = rintf(__fdiv_rn(v, s_a1));
            t = fminf(fmaxf(t, 0.f), 15.f);
            float t2 = rintf(__fdiv_rn(t * s_a1, s_in));
            g_lut1h[i] = f2h(fminf(fmaxf(t2, -8.f), 7.f));
        }
        if (i < 32257) {
            float s_a2 = ps_a2[0];
            float v = (float)(i - 16128) * (s_in * sw2);
            float t = rintf(__fdiv_rn(v, s_a2));
            t = fminf(fmaxf(t, 0.f), 15.f);
            float t2 = rintf(__fdiv_rn(t * s_a2, s_in));
            g_lut2h[i] = f2h(fminf(fmaxf(t2, -8.f), 7.f));
        }
        if (i < 179201) {
            float s_a3 = ps_a3[0];
            float v = (float)(i - 89600) * (s_in * sw3);
            float t = rintf(__fdiv_rn(v, s_a3));
            g_lut3[i] = (int8_t)fminf(fmaxf(t, 0.f), 15.f);
        }
    }
}

// ---------------------------------------------------------------------------
// conv1: quantize x -> 3x3 conv via dp4a -> integer pool-max -> fp16 LUT.
__global__ void __launch_bounds__(256) k_conv1(const float* __restrict__ x,
                                               const float* __restrict__ ps_in) {
    __shared__ __align__(4) int8_t sx[28 * 32];
    __shared__ int swa[32][3], swb[32][3];
    __shared__ uint16_t slut[1009];
    int b = blockIdx.x, tid = threadIdx.x;
    float s_in = ps_in[0];
    const float* xb = x + b * 784;
    for (int i = tid; i < 784; i += 256) {
        float t = rintf(__fdiv_rn(xb[i], s_in));
        t = fminf(fmaxf(t, -8.f), 7.f);
        sx[(i / 28) * 32 + (i % 28)] = (int8_t)t;
    }
    if (tid < 96) {
        int c = tid / 3, ky = tid % 3;
        int w0 = (int)g_w1q[c * 9 + ky * 3] & 0xff;
        int w1 = (int)g_w1q[c * 9 + ky * 3 + 1] & 0xff;
        int w2 = (int)g_w1q[c * 9 + ky * 3 + 2] & 0xff;
        swa[c][ky] = w0 | (w1 << 8) | (w2 << 16);
        swb[c][ky] = (w0 << 8) | (w1 << 16) | (w2 << 24);
    }
    for (int i = tid; i < 1009; i += 256) slut[i] = g_lut1h[i];
    __syncthreads();

    int ch = tid & 31, wq = tid >> 5;
    int wA0 = swa[ch][0], wA1 = swa[ch][1], wA2 = swa[ch][2];
    int wB0 = swb[ch][0], wB1 = swb[ch][1], wB2 = swb[ch][2];
    const int* sxw = (const int*)sx;

    for (int it = 0; it < 22; it++) {
        int win = wq + it * 8;
        if (win >= 169) break;
        int ph = win / 13, pw = win % 13;
        int bytec = 2 * pw, widx = bytec >> 2, sh = bytec & 3;
        int r0 = 2 * ph;
        int rows[4];
#pragma unroll
        for (int r = 0; r < 4; r++) {
            int u = sxw[(r0 + r) * 8 + widx];
            int v = sxw[(r0 + r) * 8 + widx + 1];
            rows[r] = sh ? __byte_perm(u, v, 0x5432) : u;
        }
        int a00 = __dp4a(rows[0], wA0, __dp4a(rows[1], wA1, __dp4a(rows[2], wA2, 0)));
        int a01 = __dp4a(rows[0], wB0, __dp4a(rows[1], wB1, __dp4a(rows[2], wB2, 0)));
        int a10 = __dp4a(rows[1], wA0, __dp4a(rows[2], wA1, __dp4a(rows[3], wA2, 0)));
        int a11 = __dp4a(rows[1], wB0, __dp4a(rows[2], wB1, __dp4a(rows[3], wB2, 0)));
        int amax = max(max(a00, a01), max(a10, a11));
        g_a1h[(b * 169 + win) * 32 + ch] = slut[amax + 504];
    }
}

// ---------------------------------------------------------------------------
__device__ __forceinline__ void ldm_x4(uint32_t addr, uint32_t* r) {
    asm volatile("ldmatrix.sync.aligned.m8n8.x4.shared.b16 {%0,%1,%2,%3}, [%4];"
                 : "=r"(r[0]), "=r"(r[1]), "=r"(r[2]), "=r"(r[3]) : "r"(addr));
}
__device__ __forceinline__ void mma_f16(float* c, const uint32_t* a,
                                        uint32_t b0, uint32_t b1) {
    asm volatile(
        "mma.sync.aligned.m16n8k16.row.col.f32.f16.f16.f32 "
        "{%0,%1,%2,%3}, {%4,%5,%6,%7}, {%8,%9}, {%0,%1,%2,%3};"
        : "+f"(c[0]), "+f"(c[1]), "+f"(c[2]), "+f"(c[3])
        : "r"(a[0]), "r"(a[1]), "r"(a[2]), "r"(a[3]), "r"(b0), "r"(b1));
}
#define CPASYNC16(dst, src) \
    asm volatile("cp.async.cg.shared.global [%0], [%1], 16;" \
                 :: "r"(dst), "l"(src) : "memory")
#define CP_COMMIT() asm volatile("cp.async.commit_group;" ::: "memory")

// ---------------------------------------------------------------------------
// conv2 fp16 implicit-GEMM, 2 images/CTA: per k-step B fragments loaded ONCE
// and reused for both images (halves B-side LDS). Images at pixel stride 80B.
// smem: img0 @0 (13568), img1 @13568, B @27136 (40960) = 68096.
__global__ void __launch_bounds__(256, 2) k_conv2() {
    extern __shared__ __align__(128) int8_t dyn2[];
    const uint32_t smem = (uint32_t)__cvta_generic_to_shared(dyn2);
    int b0 = blockIdx.x * 2, tid = threadIdx.x;
    int lane = tid & 31, wid = tid >> 5;

    {   // stage B: 2560 16B segs, 10/thread
        const int8_t* src = g_w2h + tid * 16;
        uint32_t dst = smem + 27136 + tid * 16;
#pragma unroll
        for (int i = 0; i < 10; i++)
            CPASYNC16(dst + i * 4096, src + i * 4096);
    }
    {   // stage both images: 2x676 segs, 64B/pixel -> 80B/pixel stride
        const int8_t* img = (const int8_t*)g_a1h + (size_t)b0 * 10816;
        for (int i = tid; i < 1352; i += 256) {
            int im = i >= 676, j = i - im * 676;
            int pix = j >> 2, pl = j & 3;
            CPASYNC16(smem + im * 13568 + pix * 80 + pl * 16,
                      img + im * 10816 + j * 16);
        }
    }
    CP_COMMIT();
    asm volatile("cp.async.wait_group 0;" ::: "memory");
    __syncthreads();

    if (wid >= 7) return;
    int rl = lane & 15, pb = lane >> 4;
    int r = wid * 16 + rl;
    int win = r >> 2, dp = r & 3;
    int ph = win / 5, pw = win - ph * 5;
    int y0 = 2 * ph + (dp >> 1), x0 = 2 * pw + (dp & 1);
    uint32_t aBase0 = smem + (uint32_t)((y0 * 13 + x0) * 80 + pb * 16);
    uint32_t aBase1 = aBase0 + 13568;

    uint32_t smB = smem + 27136;
    uint32_t bBase[4], bXor[4];
#pragma unroll
    for (int bt = 0; bt < 4; bt++) {
        int rb = bt * 16 + rl;
        bBase[bt] = smB + rb * 640;
        bXor[bt] = (uint32_t)(rb & 7);
    }

    float acc0[8][4], acc1[8][4];
#pragma unroll
    for (int i = 0; i < 8; i++)
#pragma unroll
        for (int j = 0; j < 4; j++) { acc0[i][j] = 0.f; acc1[i][j] = 0.f; }

    const int tapOff80[9] = {0, 80, 160, 1040, 1120, 1200, 2080, 2160, 2240};
#pragma unroll
    for (int ks = 0; ks < 18; ks++) {
        int s = ks >> 1, kk = ks & 1;
        uint32_t toff = (uint32_t)(tapOff80[s] + kk * 32);
        uint32_t bf[4][4];
        uint32_t pl = (uint32_t)(2 * ks + pb);
#pragma unroll
        for (int bt = 0; bt < 4; bt++)
            ldm_x4(bBase[bt] + ((pl ^ bXor[bt]) << 4), bf[bt]);
        uint32_t af0[4], af1[4];
        ldm_x4(aBase0 + toff, af0);
        ldm_x4(aBase1 + toff, af1);
#pragma unroll
        for (int nt = 0; nt < 8; nt++) {
            mma_f16(acc0[nt], af0, bf[nt >> 1][nt & 1], bf[nt >> 1][(nt & 1) + 2]);
            mma_f16(acc1[nt], af1, bf[nt >> 1][nt & 1], bf[nt >> 1][(nt & 1) + 2]);
        }
    }

    int t4 = lane & 3;
    int winA = wid * 4 + (lane >> 4);
    int winB = winA + 2;
    bool st = ((lane >> 2) & 3) == 0;
#pragma unroll
    for (int im = 0; im < 2; im++) {
        float (*acc)[4] = im ? acc1 : acc0;
        uint16_t* dst = g_a2h + (size_t)(b0 + im) * 1600;
#pragma unroll
        for (int nt = 0; nt < 8; nt++) {
            float m0 = acc[nt][0], m1 = acc[nt][1];
            float m2 = acc[nt][2], m3 = acc[nt][3];
            m0 = fmaxf(m0, __shfl_xor_sync(0xffffffffu, m0, 4));
            m0 = fmaxf(m0, __shfl_xor_sync(0xffffffffu, m0, 8));
            m1 = fmaxf(m1, __shfl_xor_sync(0xffffffffu, m1, 4));
            m1 = fmaxf(m1, __shfl_xor_sync(0xffffffffu, m1, 8));
            m2 = fmaxf(m2, __shfl_xor_sync(0xffffffffu, m2, 4));
            m2 = fmaxf(m2, __shfl_xor_sync(0xffffffffu, m2, 8));
            m3 = fmaxf(m3, __shfl_xor_sync(0xffffffffu, m3, 4));
            m3 = fmaxf(m3, __shfl_xor_sync(0xffffffffu, m3, 8));
            if (st) {
                int col = nt * 8 + t4 * 2;
                if (winA < 25) {
                    dst[col * 25 + winA]       = g_lut2h[__float2int_rn(m0) + 16128];
                    dst[(col + 1) * 25 + winA] = g_lut2h[__float2int_rn(m1) + 16128];
                }
                if (winB < 25) {
                    dst[col * 25 + winB]       = g_lut2h[__float2int_rn(m2) + 16128];
                    dst[(col + 1) * 25 + winB] = g_lut2h[__float2int_rn(m3) + 16128];
                }
            }
        }
    }
}

// ---------------------------------------------------------------------------
// FC1 via fp16 mma m16n8k16 (f32 acc, exact integers). BM=128 BN=128,
// K-chunk=64 halfs (128B rows, 8 planes, swizzle p^(r&7)), 3-stage cp.async.
__global__ void __launch_bounds__(256, 2) k_fc1() {
    extern __shared__ __align__(16) int8_t dynf[];
    const uint32_t smem = (uint32_t)__cvta_generic_to_shared(dynf);
    int tid = threadIdx.x, lane = tid & 31, wid = tid >> 5;
    int wm = wid >> 2, wn = wid & 3;               // warp tile 64x32
    int m0 = blockIdx.y * 128, n0 = blockIdx.x * 128;

    int r = tid >> 1, hs = tid & 1;
    const char* aSrc = (const char*)g_a2h + (size_t)(m0 + r) * 3200 + hs * 64;
    const char* bSrc = (const char*)g_wl1h + (size_t)(n0 + r) * 3200 + hs * 64;
    uint32_t dstoff[4];
#pragma unroll
    for (int i = 0; i < 4; i++) {
        int p = hs * 4 + i;
        dstoff[i] = (uint32_t)(r * 128 + ((p ^ (r & 7)) << 4));
    }

    float acc[4][4][4];
#pragma unroll
    for (int i = 0; i < 4; i++)
#pragma unroll
        for (int j = 0; j < 4; j++)
#pragma unroll
            for (int k = 0; k < 4; k++) acc[i][j][k] = 0.f;

    int pb = lane >> 4;
    int rowf = lane & 15;
    uint32_t aAddr[4], aXor[4], bAddr[2], bXor[2];
#pragma unroll
    for (int mt = 0; mt < 4; mt++) {
        int rr = wm * 64 + mt * 16 + rowf;
        aAddr[mt] = (uint32_t)(rr * 128);
        aXor[mt] = (uint32_t)(rr & 7);
    }
#pragma unroll
    for (int bt = 0; bt < 2; bt++) {
        int rr = wn * 32 + bt * 16 + rowf;
        bAddr[bt] = (uint32_t)(rr * 128 + 16384);
        bXor[bt] = (uint32_t)(rr & 7);
    }

    auto issue = [&](int ch, int st) {
        uint32_t base = smem + (uint32_t)(st * 32768);
        const char* ag = aSrc + ch * 128;
        const char* bg = bSrc + ch * 128;
#pragma unroll
        for (int i = 0; i < 4; i++) CPASYNC16(base + dstoff[i], ag + i * 16);
#pragma unroll
        for (int i = 0; i < 4; i++)
            CPASYNC16(base + 16384 + dstoff[i], bg + i * 16);
        CP_COMMIT();
    };
    issue(0, 0);
    issue(1, 1);

    for (int chk = 0; chk < 25; chk++) {
        if (chk < 24) asm volatile("cp.async.wait_group 1;" ::: "memory");
        else          asm volatile("cp.async.wait_group 0;" ::: "memory");
        __syncthreads();
        if (chk + 2 < 25) issue(chk + 2, (chk + 2) % 3);
        uint32_t base = smem + (uint32_t)((chk % 3) * 32768);
#pragma unroll
        for (int ks = 0; ks < 4; ks++) {
            uint32_t plane = (uint32_t)(2 * ks + pb);
            uint32_t af[4][4], bf[2][4];
#pragma unroll
            for (int mt = 0; mt < 4; mt++)
                ldm_x4(base + aAddr[mt] + ((plane ^ aXor[mt]) << 4), af[mt]);
#pragma unroll
            for (int bt = 0; bt < 2; bt++)
                ldm_x4(base + bAddr[bt] + ((plane ^ bXor[bt]) << 4), bf[bt]);
#pragma unroll
            for (int mt = 0; mt < 4; mt++)
#pragma unroll
                for (int nt = 0; nt < 4; nt++)
                    mma_f16(acc[mt][nt], af[mt],
                            bf[nt >> 1][nt & 1], bf[nt >> 1][(nt & 1) + 2]);
        }
    }

    int g = lane >> 2, t4 = lane & 3;
#pragma unroll
    for (int mt = 0; mt < 4; mt++) {
#pragma unroll
        for (int nt = 0; nt < 4; nt++) {
            int mrow = m0 + wm * 64 + mt * 16 + g;
            int ncol = n0 + wn * 32 + nt * 8 + t4 * 2;
#pragma unroll
            for (int h = 0; h < 2; h++) {
                char2 o;
                o.x = g_lut3[__float2int_rn(acc[mt][nt][2 * h]) + 89600];
                o.y = g_lut3[__float2int_rn(acc[mt][nt][2 * h + 1]) + 89600];
                *(char2*)(g_a3 + (size_t)(mrow + 8 * h) * 4096 + ncol) = o;
            }
        }
    }
}

// ---------------------------------------------------------------------------
// FC2: [1024,4096] x [10,4096]^T -> f32 out. Two images per block.
__global__ void __launch_bounds__(256) k_fc2(float* __restrict__ out,
                                             const float* __restrict__ ps_a3) {
    __shared__ int red[8][10];
    int tid = threadIdx.x;
    int half = tid >> 7, t = tid & 127;
    int b = blockIdx.x * 2 + half;
    const int* aw = (const int*)g_a3 + b * 1024;
    const int* wp = (const int*)g_wl2q;
    int acc[10];
#pragma unroll
    for (int n = 0; n < 10; n++) acc[n] = 0;
    for (int k = t; k < 1024; k += 128) {
        int a = aw[k];
#pragma unroll
        for (int n = 0; n < 10; n++) acc[n] = __dp4a(a, wp[n * 1024 + k], acc[n]);
    }
#pragma unroll
    for (int n = 0; n < 10; n++)
#pragma unroll
        for (int o = 16; o > 0; o >>= 1)
            acc[n] += __shfl_xor_sync(0xffffffffu, acc[n], o);
    if ((tid & 31) == 0) {
        int w = tid >> 5;
#pragma unroll
        for (int n = 0; n < 10; n++) red[w][n] = acc[n];
    }
    __syncthreads();
    if (t < 10) {
        int w0 = half * 4;
        int s = red[w0][t] + red[w0 + 1][t] + red[w0 + 2][t] + red[w0 + 3][t];
        float s_a3 = ps_a3[0];
        float s_w = __fdiv_rn(__uint_as_float(g_absmax[3]), 7.0f);
        out[b * 10 + t] = (float)s * (s_a3 * s_w);
    }
}

// ---------------------------------------------------------------------------
extern "C" void kernel_launch(void* const* d_in, const int* in_sizes, int n_in,
                              void* d_out, int out_size) {
    const float* x    = (const float*)d_in[0];
    const float* w1   = (const float*)d_in[1];
    const float* w2   = (const float*)d_in[2];
    const float* wl1  = (const float*)d_in[3];
    const float* wl2  = (const float*)d_in[4];
    const float* s_in = (const float*)d_in[5];
    const float* s_a1 = (const float*)d_in[6];
    const float* s_a2 = (const float*)d_in[7];
    const float* s_a3 = (const float*)d_in[8];
    float* out = (float*)d_out;
    (void)in_sizes; (void)n_in; (void)out_size;

    cudaFuncSetAttribute(k_conv2, cudaFuncAttributeMaxDynamicSharedMemorySize,
                         68096);
    cudaFuncSetAttribute(k_fc1, cudaFuncAttributeMaxDynamicSharedMemorySize,
                         3 * 32768);

    k_absmax_all<<<1083, 256>>>(w1, w2, wl1, wl2);
    k_quant_all<<<7214, 256>>>(w1, w2, wl1, wl2, s_in, s_a1, s_a2, s_a3);
    k_conv1<<<1024, 256>>>(x, s_in);
    k_conv2<<<512, 256, 68096>>>();
    k_fc1<<<dim3(4096 / 128, 1024 / 128), 256, 3 * 32768>>>();
    k_fc2<<<512, 256>>>(out, s_a3);
}